// round 3
// baseline (speedup 1.0000x reference)
#include <cuda_runtime.h>

// VQ_86139864089353: per-dimension 1D vector quantization.
// ze: (B, D, 1) f32 ; e: (K, D) f32 codebook.
// out: [ z (B*D) as float | zq (B*D) as float ]  (out_size = 2*B*D)
//
// 1D NN: sort codebook per dim (stable), uniform-grid LUT -> insertion
// position of x, then EXACT fp32 distance argmin over a 5-wide sorted
// window, replicating the reference's fl((x-v)^2) compare and
// argmin-first-original-index tie-break bit-for-bit.

#define BN      262144
#define DDIM    3
#define KK      512
#define NBD     (BN * DDIM)
#define NCELL   2048
#define FLO     (-4.0f)
#define FW      (8.0f / (float)NCELL)    // 1/256, exact power of two
#define FINVW   ((float)NCELL / 8.0f)    // 256,  exact power of two

#define MBLK    256
#define MITEMS  4
#define MGRID   (BN / (MBLK * MITEMS))   // 256

__device__ float          g_sorted[DDIM][KK];
__device__ unsigned short g_orig[DDIM][KK];
__device__ unsigned short g_lut[DDIM][NCELL];

// ---------------------------------------------------------------------------
// Build: stable rank (O(K^2) in smem), scatter to sorted order, LUT.
// grid DDIM x KK threads.
// ---------------------------------------------------------------------------
__global__ void vq_build(const float* __restrict__ e) {
    const int d = blockIdx.x;
    const int k = threadIdx.x;   // 0..511

    __shared__ float s_v[KK];
    s_v[k] = e[k * DDIM + d];
    __syncthreads();

    const float v = s_v[k];
    int r = 0;
    const float4* v4 = (const float4*)s_v;
#pragma unroll 16
    for (int j4 = 0; j4 < KK / 4; ++j4) {
        float4 w = v4[j4];
        int j = j4 * 4;
        r += (w.x < v) || (w.x == v && (j + 0) < k);
        r += (w.y < v) || (w.y == v && (j + 1) < k);
        r += (w.z < v) || (w.z == v && (j + 2) < k);
        r += (w.w < v) || (w.w == v && (j + 3) < k);
    }
    __syncthreads();           // s_v reads done before reuse below

    __shared__ float          s_sorted[KK];
    __shared__ unsigned short s_org[KK];
    s_sorted[r] = v;
    s_org[r]    = (unsigned short)k;
    __syncthreads();

    g_sorted[d][k] = s_sorted[k];
    g_orig[d][k]   = s_org[k];

    // LUT: conservative lower bound on insertion position.
    // lut[c] = #{ m : sorted[m] < edge },  edge = cellLeft(c) - FW (guard cell).
    // Edges are exact dyadic (-4 + k/256), guard absorbs the single rounding
    // in the query's fl(x+4)*256 mapping.
    for (int c = k; c < NCELL; c += KK) {
        float edge = FLO + (float)c * FW - FW;
        int lo = 0, hi = KK;
        while (lo < hi) {
            int m = (lo + hi) >> 1;
            if (s_sorted[m] < edge) lo = m + 1; else hi = m;
        }
        g_lut[d][c] = (unsigned short)lo;
    }
}

// ---------------------------------------------------------------------------
// Main quantization. grid MGRID x MBLK, MITEMS b's per thread.
// ---------------------------------------------------------------------------
__global__ void __launch_bounds__(MBLK)
vq_main(const float* __restrict__ ze, float* __restrict__ out) {
    __shared__ float          s_val[DDIM][KK];
    __shared__ unsigned short s_org[DDIM][KK];
    __shared__ unsigned short s_lut[DDIM][NCELL];

    const int tid = threadIdx.x;
    for (int i = tid; i < DDIM * KK; i += MBLK) {
        ((float*)s_val)[i]          = ((const float*)g_sorted)[i];
        ((unsigned short*)s_org)[i] = ((const unsigned short*)g_orig)[i];
    }
    for (int i = tid; i < DDIM * NCELL; i += MBLK)
        ((unsigned short*)s_lut)[i] = ((const unsigned short*)g_lut)[i];
    __syncthreads();

    const int base = blockIdx.x * (MBLK * MITEMS) + tid;
#pragma unroll
    for (int it = 0; it < MITEMS; ++it) {
        const int b = base + it * MBLK;
#pragma unroll
        for (int d = 0; d < DDIM; ++d) {
            const float x = __ldg(&ze[b * DDIM + d]);

            // cell -> conservative start, then scan to insertion position
            float t = fminf(fmaxf((x - FLO) * FINVW, 0.0f), (float)(NCELL - 1));
            int i = s_lut[d][(int)t];
            while (i < KK && s_val[d][i] <= x) ++i;

            // exact fp32 argmin over sorted window [i-2, i+2], tie -> min orig
            float bestD  = __int_as_float(0x7f800000);
            int   bestO  = KK;
            float bestV  = 0.0f;
#pragma unroll
            for (int off = -2; off <= 2; ++off) {
                int j = i + off;
                j = j < 0 ? 0 : (j > KK - 1 ? KK - 1 : j);
                float v  = s_val[d][j];
                float dx = x - v;
                float dd = dx * dx;          // fl((x - e)^2), same as reference
                int   o  = s_org[d][j];
                bool take = (dd < bestD) || (dd == bestD && o < bestO);
                bestD = take ? dd : bestD;
                bestO = take ? o  : bestO;
                bestV = take ? v  : bestV;
            }

            out[b * DDIM + d]       = (float)bestO;
            out[NBD + b * DDIM + d] = bestV;
        }
    }
}

// ---------------------------------------------------------------------------
extern "C" void kernel_launch(void* const* d_in, const int* in_sizes, int n_in,
                              void* d_out, int out_size) {
    const float* ze = (const float*)d_in[0];   // (B, D, 1) = 786432 f32
    const float* e  = (const float*)d_in[1];   // (K, D)    = 1536 f32
    float* out = (float*)d_out;                // 2 * B * D f32

    vq_build<<<DDIM, KK>>>(e);
    vq_main<<<MGRID, MBLK>>>(ze, out);
}

// round 4
// speedup vs baseline: 1.1091x; 1.1091x over previous
#include <cuda_runtime.h>

// VQ_86139864089353: per-dimension 1D vector quantization.
// ze: (B, D, 1) f32 ; e: (K, D) f32.  out: [ z (B*D) f32 | zq (B*D) f32 ]
//
// Sorted codebook per dim + uniform LUT -> insertion position, then exact
// fp32 distance argmin over {i-2..i+1} with reference tie-break (min orig).

#define BN      262144
#define DDIM    3
#define KK      512
#define NBD     (BN * DDIM)          // 786432 elements per output half
#define NEL     (BN * DDIM)
#define NCELL   2048
#define FLO     (-4.0f)
#define FW      (8.0f / (float)NCELL)    // 1/256 (dyadic)
#define FINVW   ((float)NCELL / 8.0f)    // 256   (dyadic)

#define MBLK    256
#define MVEC    4                        // elements per thread (one float4)
#define MGRID   (NEL / (MBLK * MVEC))    // 768

__device__ float          g_sorted[DDIM][KK];
__device__ float2         g_pair[DDIM][KK];    // {sorted value, (float)orig}
__device__ unsigned short g_lut[DDIM][NCELL];

// ---------------------------------------------------------------------------
// Build: stable rank (O(K^2) in smem), scatter, LUT. grid DDIM x KK threads.
// ---------------------------------------------------------------------------
__global__ void vq_build(const float* __restrict__ e) {
    const int d = blockIdx.x;
    const int k = threadIdx.x;   // 0..511

    __shared__ float s_v[KK];
    s_v[k] = e[k * DDIM + d];
    __syncthreads();

    const float v = s_v[k];
    int r = 0;
    const float4* v4 = (const float4*)s_v;
#pragma unroll 16
    for (int j4 = 0; j4 < KK / 4; ++j4) {
        float4 w = v4[j4];
        int j = j4 * 4;
        r += (w.x < v) || (w.x == v && (j + 0) < k);
        r += (w.y < v) || (w.y == v && (j + 1) < k);
        r += (w.z < v) || (w.z == v && (j + 2) < k);
        r += (w.w < v) || (w.w == v && (j + 3) < k);
    }
    __syncthreads();

    __shared__ float s_sorted[KK];
    __shared__ short s_org[KK];
    s_sorted[r] = v;
    s_org[r]    = (short)k;
    __syncthreads();

    g_sorted[d][k] = s_sorted[k];
    g_pair[d][k]   = make_float2(s_sorted[k], (float)s_org[k]);

    // LUT: conservative lower bound on insertion position, one-cell guard.
    for (int c = k; c < NCELL; c += KK) {
        float edge = FLO + (float)c * FW - FW;
        int lo = 0, hi = KK;
        while (lo < hi) {
            int m = (lo + hi) >> 1;
            if (s_sorted[m] < edge) lo = m + 1; else hi = m;
        }
        g_lut[d][c] = (unsigned short)lo;
    }
}

// ---------------------------------------------------------------------------
// Main: each thread: 1 LDG.128 (4 elements), LUT+scan+4-candidate exact
// argmin per element, 2 STG.128.
// ---------------------------------------------------------------------------
__global__ void __launch_bounds__(MBLK)
vq_main(const float4* __restrict__ ze4, float* __restrict__ out) {
    __shared__ float          s_val[DDIM][KK];
    __shared__ float2         s_pair[DDIM][KK];
    __shared__ unsigned short s_lut[DDIM][NCELL];

    const int tid = threadIdx.x;
    // preload tables (vectorized)
    {
        const float4* src = (const float4*)g_sorted;
        float4*       dst = (float4*)s_val;
        for (int i = tid; i < DDIM * KK / 4; i += MBLK) dst[i] = src[i];
    }
    {
        const float4* src = (const float4*)g_pair;
        float4*       dst = (float4*)s_pair;
        for (int i = tid; i < DDIM * KK * 2 / 4; i += MBLK) dst[i] = src[i];
    }
    {
        const uint4* src = (const uint4*)g_lut;
        uint4*       dst = (uint4*)s_lut;
        for (int i = tid; i < DDIM * NCELL / 8; i += MBLK) dst[i] = src[i];
    }
    __syncthreads();

    const int t  = blockIdx.x * MBLK + tid;      // float4 index
    const int n0 = t * MVEC;                     // first element index
    float4 xv = ze4[t];
    float xs[MVEC] = {xv.x, xv.y, xv.z, xv.w};
    float rz[MVEC], rq[MVEC];

    int d = n0 % 3;
#pragma unroll
    for (int j = 0; j < MVEC; ++j) {
        const float x = xs[j];

        float tt = fminf(fmaxf((x - FLO) * FINVW, 0.0f), (float)(NCELL - 1));
        int i = s_lut[d][(int)tt];
        while (i < KK && s_val[d][i] <= x) ++i;

        float bestD = __int_as_float(0x7f800000);
        float bestO = 1.0e9f;
        float bestV = 0.0f;
#pragma unroll
        for (int off = -2; off <= 1; ++off) {
            int c = i + off;
            c = c < 0 ? 0 : (c > KK - 1 ? KK - 1 : c);
            float2 p = s_pair[d][c];
            float dx = x - p.x;
            float dd = dx * dx;                  // same fp32 op as reference
            bool take = (dd < bestD) || (dd == bestD && p.y < bestO);
            bestD = take ? dd : bestD;
            bestO = take ? p.y : bestO;
            bestV = take ? p.x : bestV;
        }
        rz[j] = bestO;
        rq[j] = bestV;

        d = (d == 2) ? 0 : d + 1;
    }

    ((float4*)out)[t]               = make_float4(rz[0], rz[1], rz[2], rz[3]);
    ((float4*)(out + NBD))[t]       = make_float4(rq[0], rq[1], rq[2], rq[3]);
}

// ---------------------------------------------------------------------------
extern "C" void kernel_launch(void* const* d_in, const int* in_sizes, int n_in,
                              void* d_out, int out_size) {
    const float* ze = (const float*)d_in[0];   // (B, D, 1)
    const float* e  = (const float*)d_in[1];   // (K, D)
    float* out = (float*)d_out;

    vq_build<<<DDIM, KK>>>(e);
    vq_main<<<MGRID, MBLK>>>((const float4*)ze, out);
}

// round 5
// speedup vs baseline: 1.3050x; 1.1767x over previous
#include <cuda_runtime.h>

// VQ_86139864089353: per-dimension 1D vector quantization.
// ze: (B, D, 1) f32 ; e: (K, D) f32.  out: [ z (B*D) f32 | zq (B*D) f32 ]
//
// Sorted codebook per dim + uniform LUT -> insertion position, then exact
// fp32 distance argmin over {i-2..i+1} with reference tie-break (min orig).

#define BN      262144
#define DDIM    3
#define KK      512
#define NBD     (BN * DDIM)          // elements per output half
#define NEL     (BN * DDIM)
#define NCELL   2048
#define FLO     (-4.0f)
#define FW      (8.0f / (float)NCELL)    // 1/256 (dyadic)
#define FINVW   ((float)NCELL / 8.0f)    // 256   (dyadic)
#define JPARTS  4
#define JCH     (KK / JPARTS)            // 128

#define MBLK    512
#define MVEC    2                        // elements per thread (one float2)
#define MGRID   (NEL / (MBLK * MVEC))    // 768

__device__ int            g_rankp[DDIM][JPARTS][KK];
__device__ float          g_sorted[DDIM][KK];
__device__ float2         g_pair[DDIM][KK];    // {sorted value, (float)orig}
__device__ unsigned short g_lut[DDIM][NCELL];

// ---------------------------------------------------------------------------
// Kernel 1: partial stable ranks. grid (DDIM, JPARTS) x 512 threads.
// ---------------------------------------------------------------------------
__global__ void vq_rank(const float* __restrict__ e) {
    const int d = blockIdx.x;
    const int p = blockIdx.y;
    const int k = threadIdx.x;

    __shared__ float sv[JCH];
    if (k < JCH) sv[k] = e[(p * JCH + k) * DDIM + d];
    __syncthreads();

    const float v = e[k * DDIM + d];
    const int jb = p * JCH;
    int r = 0;
    const float4* s4 = (const float4*)sv;
#pragma unroll 8
    for (int j4 = 0; j4 < JCH / 4; ++j4) {
        float4 w = s4[j4];
        int j = jb + j4 * 4;
        r += (w.x < v) || (w.x == v && (j + 0) < k);
        r += (w.y < v) || (w.y == v && (j + 1) < k);
        r += (w.z < v) || (w.z == v && (j + 2) < k);
        r += (w.w < v) || (w.w == v && (j + 3) < k);
    }
    g_rankp[d][p][k] = r;
}

// ---------------------------------------------------------------------------
// Kernel 2: combine ranks, scatter to sorted order, LUT. grid DDIM x KK.
// ---------------------------------------------------------------------------
__global__ void vq_build(const float* __restrict__ e) {
    const int d = blockIdx.x;
    const int k = threadIdx.x;   // 0..511

    __shared__ float s_sorted[KK];
    __shared__ short s_org[KK];

    int r = g_rankp[d][0][k] + g_rankp[d][1][k]
          + g_rankp[d][2][k] + g_rankp[d][3][k];
    float v = e[k * DDIM + d];
    s_sorted[r] = v;
    s_org[r]    = (short)k;
    __syncthreads();

    g_sorted[d][k] = s_sorted[k];
    g_pair[d][k]   = make_float2(s_sorted[k], (float)s_org[k]);

    // LUT: conservative lower bound on insertion position, one-cell guard.
    for (int c = k; c < NCELL; c += KK) {
        float edge = FLO + (float)c * FW - FW;
        int lo = 0, hi = KK;
        while (lo < hi) {
            int m = (lo + hi) >> 1;
            if (s_sorted[m] < edge) lo = m + 1; else hi = m;
        }
        g_lut[d][c] = (unsigned short)lo;
    }
}

// ---------------------------------------------------------------------------
// Kernel 3: main. 2 elements/thread, 512-thread blocks -> 64 warps/SM.
// ---------------------------------------------------------------------------
__global__ void __launch_bounds__(MBLK, 4)
vq_main(const float2* __restrict__ ze2, float* __restrict__ out) {
    __shared__ float          s_val[DDIM][KK];
    __shared__ float2         s_pair[DDIM][KK];
    __shared__ unsigned short s_lut[DDIM][NCELL];

    const int tid = threadIdx.x;
    // preload tables (vectorized)
    {
        const float4* src = (const float4*)g_sorted;
        float4*       dst = (float4*)s_val;
        for (int i = tid; i < DDIM * KK / 4; i += MBLK) dst[i] = src[i];
    }
    {
        const float4* src = (const float4*)g_pair;
        float4*       dst = (float4*)s_pair;
        for (int i = tid; i < DDIM * KK * 2 / 4; i += MBLK) dst[i] = src[i];
    }
    {
        const uint4* src = (const uint4*)g_lut;
        uint4*       dst = (uint4*)s_lut;
        for (int i = tid; i < DDIM * NCELL / 8; i += MBLK) dst[i] = src[i];
    }
    __syncthreads();

    const int t  = blockIdx.x * MBLK + tid;      // float2 index
    const int n0 = t * MVEC;                     // first element index
    float2 xv = ze2[t];
    float xs[MVEC] = {xv.x, xv.y};
    float rz[MVEC], rq[MVEC];

    int d = n0 % 3;
#pragma unroll
    for (int j = 0; j < MVEC; ++j) {
        const float x = xs[j];

        float tt = fminf(fmaxf((x - FLO) * FINVW, 0.0f), (float)(NCELL - 1));
        int i = s_lut[d][(int)tt];
        while (i < KK && s_val[d][i] <= x) ++i;

        // exact fp32 argmin over sorted window [i-2, i+1], tie -> min orig
        float bestD = __int_as_float(0x7f800000);
        float bestO = 1.0e9f;
        float bestV = 0.0f;
#pragma unroll
        for (int off = -2; off <= 1; ++off) {
            int c = i + off;
            c = c < 0 ? 0 : (c > KK - 1 ? KK - 1 : c);
            float2 p = s_pair[d][c];
            float dx = x - p.x;
            float dd = dx * dx;                  // same fp32 op as reference
            bool take = (dd < bestD) || (dd == bestD && p.y < bestO);
            bestD = take ? dd : bestD;
            bestO = take ? p.y : bestO;
            bestV = take ? p.x : bestV;
        }
        rz[j] = bestO;
        rq[j] = bestV;

        d = (d == 2) ? 0 : d + 1;
    }

    ((float2*)out)[t]         = make_float2(rz[0], rz[1]);
    ((float2*)(out + NBD))[t] = make_float2(rq[0], rq[1]);
}

// ---------------------------------------------------------------------------
extern "C" void kernel_launch(void* const* d_in, const int* in_sizes, int n_in,
                              void* d_out, int out_size) {
    const float* ze = (const float*)d_in[0];   // (B, D, 1)
    const float* e  = (const float*)d_in[1];   // (K, D)
    float* out = (float*)d_out;

    vq_rank<<<dim3(DDIM, JPARTS), KK>>>(e);
    vq_build<<<DDIM, KK>>>(e);
    vq_main<<<MGRID, MBLK>>>((const float2*)ze, out);
}

// round 6
// speedup vs baseline: 1.5204x; 1.1650x over previous
#include <cuda_runtime.h>

// VQ_86139864089353: per-dimension 1D vector quantization.
// ze: (B, D, 1) f32 ; e: (K, D) f32.  out: [ z (B*D) f32 | zq (B*D) f32 ]
//
// Sorted codebook per dim + uniform LUT -> insertion position, then exact
// fp32 distance argmin over {i-2..i+1} with reference tie-break (min orig).

#define BN      262144
#define DDIM    3
#define KK      512
#define NBD     (BN * DDIM)
#define NEL     (BN * DDIM)
#define NCELL   2048
#define FLO     (-4.0f)
#define FW      (8.0f / (float)NCELL)    // 1/256 (dyadic)
#define FINVW   ((float)NCELL / 8.0f)    // 256   (dyadic)
#define JPARTS  16
#define JCH     (KK / JPARTS)            // 32

#define MBLK    512
#define MVEC    2
#define MGRID   (NEL / (MBLK * MVEC))    // 768

__device__ int            g_rankp[DDIM][JPARTS][KK];
__device__ float2         g_pair[DDIM][KK];    // {sorted value, (float)orig}
__device__ unsigned short g_lut[DDIM][NCELL];

// Monotone (order-preserving) uint32 map of an IEEE754 float.
__device__ __forceinline__ unsigned fkey(float f) {
    unsigned u = __float_as_uint(f);
    return u ^ ((unsigned)((int)u >> 31) | 0x80000000u);
}

// ---------------------------------------------------------------------------
// Kernel 1: partial stable ranks via 64-bit keys. grid (DDIM, JPARTS) x 512.
// key = mono(value):index  ->  (kj < kk) == (vj<vk || (vj==vk && j<k))
// ---------------------------------------------------------------------------
__global__ void vq_rank(const float* __restrict__ e) {
    const int d = blockIdx.x;
    const int p = blockIdx.y;
    const int k = threadIdx.x;

    __shared__ unsigned long long s_k[JCH];
    if (k < JCH) {
        int j = p * JCH + k;
        s_k[k] = ((unsigned long long)fkey(e[j * DDIM + d]) << 16) | (unsigned)j;
    }
    __syncthreads();

    const unsigned long long kv =
        ((unsigned long long)fkey(e[k * DDIM + d]) << 16) | (unsigned)k;
    int r = 0;
#pragma unroll
    for (int j = 0; j < JCH; ++j)
        r += (s_k[j] < kv);
    g_rankp[d][p][k] = r;
}

// ---------------------------------------------------------------------------
// Kernel 2: combine partials, scatter to sorted order, LUT. grid DDIM x KK.
// ---------------------------------------------------------------------------
__global__ void vq_build(const float* __restrict__ e) {
    const int d = blockIdx.x;
    const int k = threadIdx.x;   // 0..511

    int r = 0;
#pragma unroll
    for (int p = 0; p < JPARTS; ++p)
        r += g_rankp[d][p][k];

    __shared__ float s_sorted[KK];
    __shared__ short s_org[KK];
    s_sorted[r] = e[k * DDIM + d];
    s_org[r]    = (short)k;
    __syncthreads();

    g_pair[d][k] = make_float2(s_sorted[k], (float)s_org[k]);

    // LUT: conservative lower bound on insertion position, one-cell guard.
    for (int c = k; c < NCELL; c += KK) {
        float edge = FLO + (float)c * FW - FW;
        int lo = 0, hi = KK;
        while (lo < hi) {
            int m = (lo + hi) >> 1;
            if (s_sorted[m] < edge) lo = m + 1; else hi = m;
        }
        g_lut[d][c] = (unsigned short)lo;
    }
}

// ---------------------------------------------------------------------------
// Kernel 3: main. 2 elements/thread, 512-thread blocks.
// ---------------------------------------------------------------------------
__global__ void __launch_bounds__(MBLK, 4)
vq_main(const float2* __restrict__ ze2, float* __restrict__ out) {
    __shared__ float2         s_pair[DDIM][KK];
    __shared__ unsigned short s_lut[DDIM][NCELL];

    const int tid = threadIdx.x;
    {
        const float4* src = (const float4*)g_pair;
        float4*       dst = (float4*)s_pair;
        for (int i = tid; i < DDIM * KK * 2 / 4; i += MBLK) dst[i] = src[i];
    }
    {
        const uint4* src = (const uint4*)g_lut;
        uint4*       dst = (uint4*)s_lut;
        for (int i = tid; i < DDIM * NCELL / 8; i += MBLK) dst[i] = src[i];
    }
    __syncthreads();

    const int t  = blockIdx.x * MBLK + tid;      // float2 index
    const int n0 = t * MVEC;
    float2 xv = ze2[t];
    float xs[MVEC] = {xv.x, xv.y};
    float rz[MVEC], rq[MVEC];

    int d = n0 % 3;
#pragma unroll
    for (int j = 0; j < MVEC; ++j) {
        const float x = xs[j];

        float tt = fminf(fmaxf((x - FLO) * FINVW, 0.0f), (float)(NCELL - 1));
        int i = s_lut[d][(int)tt];
        while (i < KK && s_pair[d][i].x <= x) ++i;

        // exact fp32 argmin over sorted window [i-2, i+1], tie -> min orig
        float bestD = __int_as_float(0x7f800000);
        float bestO = 1.0e9f;
        float bestV = 0.0f;
#pragma unroll
        for (int off = -2; off <= 1; ++off) {
            int c = i + off;
            c = c < 0 ? 0 : (c > KK - 1 ? KK - 1 : c);
            float2 p = s_pair[d][c];
            float dx = x - p.x;
            float dd = dx * dx;                  // same fp32 op as reference
            bool take = (dd < bestD) || (dd == bestD && p.y < bestO);
            bestD = take ? dd : bestD;
            bestO = take ? p.y : bestO;
            bestV = take ? p.x : bestV;
        }
        rz[j] = bestO;
        rq[j] = bestV;

        d = (d == 2) ? 0 : d + 1;
    }

    ((float2*)out)[t]         = make_float2(rz[0], rz[1]);
    ((float2*)(out + NBD))[t] = make_float2(rq[0], rq[1]);
}

// ---------------------------------------------------------------------------
extern "C" void kernel_launch(void* const* d_in, const int* in_sizes, int n_in,
                              void* d_out, int out_size) {
    const float* ze = (const float*)d_in[0];   // (B, D, 1)
    const float* e  = (const float*)d_in[1];   // (K, D)
    float* out = (float*)d_out;

    vq_rank<<<dim3(DDIM, JPARTS), KK>>>(e);
    vq_build<<<DDIM, KK>>>(e);
    vq_main<<<MGRID, MBLK>>>((const float2*)ze, out);
}